// round 5
// baseline (speedup 1.0000x reference)
#include <cuda_runtime.h>
#include <cstdint>

// Problem constants (fixed by the reference)
#define NN   100000
#define INF  128
#define HH   4
#define DD   32
#define HD   128        // H*D
#define RR   3
#define EE   800000
#define NEG  0.2f

#define NTOT (RR * NN)            // 300000 (r,dst) buckets
#define SCAN_BLK 1024
#define NBLK ((NTOT + SCAN_BLK - 1) / SCAN_BLK)   // 293

// ---------------- scratch (static device globals; no allocation allowed) ----
__device__ float g_fs[(size_t)RR * NN * HD];    // 153.6 MB
__device__ float g_fd[(size_t)RR * NN * HD];    // 153.6 MB
__device__ int   g_cnt[NTOT];                   // in-degree per (r,dst)
__device__ int   g_off[NTOT];                   // exclusive prefix (mutated by fill)
__device__ int   g_esrc[RR * EE];               // src ids bucketed by (r,dst)
__device__ int   g_bsum[512];                   // scan block totals
__device__ int   g_bpre[512];                   // scanned block totals

// ---------------- helpers ---------------------------------------------------
__device__ __forceinline__ float f2tf32(float x) {
    uint32_t o;
    asm("cvt.rna.tf32.f32 %0, %1;" : "=r"(o) : "f"(x));
    return __uint_as_float(o);
}

__device__ __forceinline__ void mma_tf32(float c[4],
                                         uint32_t a0, uint32_t a1,
                                         uint32_t a2, uint32_t a3,
                                         uint32_t b0, uint32_t b1) {
    asm volatile(
        "mma.sync.aligned.m16n8k8.row.col.f32.tf32.tf32.f32 "
        "{%0,%1,%2,%3}, {%4,%5,%6,%7}, {%8,%9}, {%0,%1,%2,%3};"
        : "+f"(c[0]), "+f"(c[1]), "+f"(c[2]), "+f"(c[3])
        : "r"(a0), "r"(a1), "r"(a2), "r"(a3), "r"(b0), "r"(b1));
}

// ---------------- CSR build -------------------------------------------------
__global__ void k_count(const int* __restrict__ dst_idx) {
    int gw = blockIdx.x * blockDim.x + threadIdx.x;
    if (gw >= RR * EE) return;
    int r = gw / EE;
    atomicAdd(&g_cnt[r * NN + dst_idx[gw]], 1);
}

// Hillis-Steele block scans (exclusive): partials + block totals
__global__ __launch_bounds__(SCAN_BLK) void k_scan1() {
    __shared__ int s[SCAN_BLK];
    int t = threadIdx.x;
    int i = blockIdx.x * SCAN_BLK + t;
    int v = (i < NTOT) ? g_cnt[i] : 0;
    s[t] = v;
    __syncthreads();
#pragma unroll
    for (int d = 1; d < SCAN_BLK; d <<= 1) {
        int x = (t >= d) ? s[t - d] : 0;
        __syncthreads();
        s[t] += x;
        __syncthreads();
    }
    if (i < NTOT) g_off[i] = s[t] - v;          // exclusive
    if (t == SCAN_BLK - 1) g_bsum[blockIdx.x] = s[t];
}

__global__ __launch_bounds__(512) void k_scan2() {
    __shared__ int s[512];
    int t = threadIdx.x;
    int v = (t < NBLK) ? g_bsum[t] : 0;
    s[t] = v;
    __syncthreads();
#pragma unroll
    for (int d = 1; d < 512; d <<= 1) {
        int x = (t >= d) ? s[t - d] : 0;
        __syncthreads();
        s[t] += x;
        __syncthreads();
    }
    g_bpre[t] = s[t] - v;                        // exclusive
}

__global__ __launch_bounds__(SCAN_BLK) void k_scan3() {
    int i = blockIdx.x * SCAN_BLK + threadIdx.x;
    if (i < NTOT) g_off[i] += g_bpre[blockIdx.x];
}

// Bucket fill. Mutates g_off: afterwards g_off[b] == bucket end.
__global__ void k_fill(const int* __restrict__ src_idx,
                       const int* __restrict__ dst_idx) {
    int gw = blockIdx.x * blockDim.x + threadIdx.x;
    if (gw >= RR * EE) return;
    int r = gw / EE;
    int pos = atomicAdd(&g_off[r * NN + dst_idx[gw]], 1);
    g_esrc[pos] = src_idx[gw];
}

// ---------------- tf32 tensor-core GEMM: fs/fd = h @ W + b ------------------
// Grid = (6 mats, row-blocks): the 6 blocks sharing an A-tile are CONCURRENT
// (x enumerates fastest), so h row-blocks are read from DRAM once and hit L2
// for the other 5 matrices.
__global__ __launch_bounds__(256) void rgat_gemm_tc(
    const float* __restrict__ hmat,
    const float* __restrict__ Wsrc, const float* __restrict__ bsrc,
    const float* __restrict__ Wdst, const float* __restrict__ bdst) {
    const int mat = blockIdx.x;          // 0..5  (fast dimension)
    const int r   = mat >> 1;
    const bool isdst = (mat & 1);
    const float* W    = (isdst ? Wdst : Wsrc) + r * INF * HD;
    const float* bvec = (isdst ? bdst : bsrc) + r * HD;
    float* out = (isdst ? g_fd : g_fs) + (size_t)r * NN * HD;

    __shared__ float As[128][36];    // A frag LDS: 4*gid+tig -> conflict-free
    __shared__ float Bs[32][136];    // B frag LDS: 8*tig+gid -> conflict-free

    const int tid  = threadIdx.x;
    const int warp = tid >> 5;
    const int lane = tid & 31;
    const int gid  = lane >> 2;
    const int tig  = lane & 3;
    const int row0 = blockIdx.y * 128;
    const int wrow = warp * 16;

    float c[16][4];
#pragma unroll
    for (int nt = 0; nt < 16; nt++)
#pragma unroll
        for (int j = 0; j < 4; j++) c[nt][j] = 0.f;

    for (int k0 = 0; k0 < INF; k0 += 32) {
#pragma unroll
        for (int i = 0; i < 4; i++) {
            int idx = tid + 256 * i;
            int rr = idx >> 3, cc = (idx & 7) * 4;
            int grow = row0 + rr;
            float4 v = make_float4(0.f, 0.f, 0.f, 0.f);
            if (grow < NN)
                v = *(const float4*)&hmat[(size_t)grow * INF + k0 + cc];
            float4 t;
            t.x = f2tf32(v.x); t.y = f2tf32(v.y);
            t.z = f2tf32(v.z); t.w = f2tf32(v.w);
            *(float4*)&As[rr][cc] = t;
        }
#pragma unroll
        for (int i = 0; i < 4; i++) {
            int idx = tid + 256 * i;
            int kr = idx >> 5, cc = (idx & 31) * 4;
            float4 v = *(const float4*)&W[(size_t)(k0 + kr) * HD + cc];
            float4 t;
            t.x = f2tf32(v.x); t.y = f2tf32(v.y);
            t.z = f2tf32(v.z); t.w = f2tf32(v.w);
            *(float4*)&Bs[kr][cc] = t;
        }
        __syncthreads();
#pragma unroll
        for (int ks = 0; ks < 4; ks++) {
            const int kk = ks * 8;
            uint32_t a0 = __float_as_uint(As[wrow + gid    ][kk + tig    ]);
            uint32_t a1 = __float_as_uint(As[wrow + gid + 8][kk + tig    ]);
            uint32_t a2 = __float_as_uint(As[wrow + gid    ][kk + tig + 4]);
            uint32_t a3 = __float_as_uint(As[wrow + gid + 8][kk + tig + 4]);
#pragma unroll
            for (int nt = 0; nt < 16; nt++) {
                const int n = nt * 8 + gid;
                uint32_t b0 = __float_as_uint(Bs[kk + tig    ][n]);
                uint32_t b1 = __float_as_uint(Bs[kk + tig + 4][n]);
                mma_tf32(c[nt], a0, a1, a2, a3, b0, b1);
            }
        }
        __syncthreads();
    }

    const int orow = row0 + wrow + gid;
#pragma unroll
    for (int nt = 0; nt < 16; nt++) {
        const int col = nt * 8 + tig * 2;
        float2 bb = *(const float2*)&bvec[col];
        if (orow < NN) {
            float2 v = make_float2(c[nt][0] + bb.x, c[nt][1] + bb.y);
            *(float2*)&out[(size_t)orow * HD + col] = v;
        }
        if (orow + 8 < NN) {
            float2 v = make_float2(c[nt][2] + bb.x, c[nt][3] + bb.y);
            *(float2*)&out[(size_t)(orow + 8) * HD + col] = v;
        }
    }
}

// ---------------- pull-mode aggregation: warp per destination node ----------
// Depth-4 software pipeline on the fs row gathers (MLP 4). fd[dst] read once
// per (r,dst); denominator + message accumulator in registers; single store.
__global__ __launch_bounds__(256) void rgat_agg(
    const float* __restrict__ attn, const float* __restrict__ bias,
    float* __restrict__ out) {
    const int dstn = (blockIdx.x * blockDim.x + threadIdx.x) >> 5;
    const int lane = threadIdx.x & 31;
    if (dstn >= NN) return;

    float4 tot;
    {   // start from summed bias
        float4 b0 = ((const float4*)(bias         ))[lane];
        float4 b1 = ((const float4*)(bias +     HD))[lane];
        float4 b2 = ((const float4*)(bias + 2 * HD))[lane];
        tot = make_float4(b0.x + b1.x + b2.x, b0.y + b1.y + b2.y,
                          b0.z + b1.z + b2.z, b0.w + b1.w + b2.w);
    }

#pragma unroll
    for (int r = 0; r < RR; r++) {
        const int bkt = r * NN + dstn;
        const int end = g_off[bkt];          // post-fill == bucket end
        const int cnt = g_cnt[bkt];
        if (cnt == 0) continue;
        const int beg = end - cnt;

        const float4 fd4 = ((const float4*)(g_fd + ((size_t)bkt) * HD))[lane];
        const float4 av  = ((const float4*)(attn + r * HD))[lane];
        const float* fsr = g_fs + (size_t)r * NN * HD;

        float4 acc = make_float4(0.f, 0.f, 0.f, 0.f);
        float den = 0.f;

        for (int e0 = beg; e0 < end; e0 += 32) {
            const int m = min(32, end - e0);
            int mysrc = (lane < m) ? g_esrc[e0 + lane] : 0;

            int j = 0;
            while (j < m) {
                const int b = min(4, m - j);
                float4 rowv[4];
                // batch the gathers: 4 independent LDG.128 in flight
#pragma unroll
                for (int i = 0; i < 4; i++) {
                    if (i < b) {
                        int s = __shfl_sync(0xFFFFFFFFu, mysrc, j + i);
                        rowv[i] = ((const float4*)(fsr + (size_t)s * HD))[lane];
                    }
                }
#pragma unroll
                for (int i = 0; i < 4; i++) {
                    if (i < b) {
                        float4 cur = rowv[i];
                        float4 v;
                        v.x = cur.x + fd4.x; v.x = v.x > 0.f ? v.x : NEG * v.x;
                        v.y = cur.y + fd4.y; v.y = v.y > 0.f ? v.y : NEG * v.y;
                        v.z = cur.z + fd4.z; v.z = v.z > 0.f ? v.z : NEG * v.z;
                        v.w = cur.w + fd4.w; v.w = v.w > 0.f ? v.w : NEG * v.w;
                        float p = v.x * av.x + v.y * av.y
                                + v.z * av.z + v.w * av.w;
                        p += __shfl_xor_sync(0xFFFFFFFFu, p, 4);
                        p += __shfl_xor_sync(0xFFFFFFFFu, p, 2);
                        p += __shfl_xor_sync(0xFFFFFFFFu, p, 1);
                        const float ex = __expf(p);  // shift-free softmax
                        den   += ex;
                        acc.x += ex * cur.x;
                        acc.y += ex * cur.y;
                        acc.z += ex * cur.z;
                        acc.w += ex * cur.w;
                    }
                }
                j += b;
            }
        }
        const float inv = 1.f / den;          // cnt>0 => den>0
        tot.x += acc.x * inv;
        tot.y += acc.y * inv;
        tot.z += acc.z * inv;
        tot.w += acc.w * inv;
    }
    ((float4*)(out + (size_t)dstn * HD))[lane] = tot;
}

// ---------------- launch -----------------------------------------------------
extern "C" void kernel_launch(void* const* d_in, const int* in_sizes, int n_in,
                              void* d_out, int out_size) {
    const float* h     = (const float*)d_in[0];
    const float* W_src = (const float*)d_in[1];
    const float* b_src = (const float*)d_in[2];
    const float* W_dst = (const float*)d_in[3];
    const float* b_dst = (const float*)d_in[4];
    const float* attn  = (const float*)d_in[5];
    const float* bias  = (const float*)d_in[6];
    const int*   src   = (const int*)d_in[7];
    const int*   dst   = (const int*)d_in[8];
    float* out = (float*)d_out;

    const int eblk = (RR * EE + 255) / 256;

    // CSR build (counting sort by (r,dst))
    void* cnt_ptr = nullptr;
    cudaGetSymbolAddress(&cnt_ptr, g_cnt);
    cudaMemsetAsync(cnt_ptr, 0, NTOT * sizeof(int));
    k_count<<<eblk, 256>>>(dst);
    k_scan1<<<NBLK, SCAN_BLK>>>();
    k_scan2<<<1, 512>>>();
    k_scan3<<<NBLK, SCAN_BLK>>>();
    k_fill<<<eblk, 256>>>(src, dst);

    // fs/fd tf32 tensor-core GEMMs; mat on x so A-tile sharers are concurrent
    dim3 ggrid(2 * RR, (NN + 127) / 128);
    rgat_gemm_tc<<<ggrid, 256>>>(h, W_src, b_src, W_dst, b_dst);

    // pull-mode aggregation: warp per destination node
    rgat_agg<<<(NN * 32 + 255) / 256, 256>>>(attn, bias, out);
}

// round 6
// speedup vs baseline: 1.3502x; 1.3502x over previous
#include <cuda_runtime.h>
#include <cuda_fp16.h>
#include <cstdint>

// Problem constants (fixed by the reference)
#define NN   100000
#define INF  128
#define HH   4
#define DD   32
#define HD   128        // H*D
#define RR   3
#define EE   800000
#define NEG  0.2f

#define NTOT (RR * NN)            // 300000 (r,dst) buckets
#define SCAN_BLK 1024
#define NBLK ((NTOT + SCAN_BLK - 1) / SCAN_BLK)   // 293

// ---------------- scratch (static device globals; no allocation allowed) ----
__device__ __half g_fs[(size_t)RR * NN * HD];   // 76.8 MB (fp16 storage)
__device__ __half g_fd[(size_t)RR * NN * HD];   // 76.8 MB
__device__ int    g_cnt[NTOT];
__device__ int    g_off[NTOT];                  // exclusive prefix (mutated by fill)
__device__ int    g_esrc[RR * EE];              // src ids bucketed by (r,dst)
__device__ int    g_bsum[512];
__device__ int    g_bpre[512];

// ---------------- helpers ---------------------------------------------------
__device__ __forceinline__ float f2tf32(float x) {
    uint32_t o;
    asm("cvt.rna.tf32.f32 %0, %1;" : "=r"(o) : "f"(x));
    return __uint_as_float(o);
}

__device__ __forceinline__ void mma_tf32(float c[4],
                                         uint32_t a0, uint32_t a1,
                                         uint32_t a2, uint32_t a3,
                                         uint32_t b0, uint32_t b1) {
    asm volatile(
        "mma.sync.aligned.m16n8k8.row.col.f32.tf32.tf32.f32 "
        "{%0,%1,%2,%3}, {%4,%5,%6,%7}, {%8,%9}, {%0,%1,%2,%3};"
        : "+f"(c[0]), "+f"(c[1]), "+f"(c[2]), "+f"(c[3])
        : "r"(a0), "r"(a1), "r"(a2), "r"(a3), "r"(b0), "r"(b1));
}

// load 4 consecutive halves as float4 (one LDG.64)
__device__ __forceinline__ float4 ldh4(const __half* p) {
    uint2 u = *(const uint2*)p;
    __half2 h0 = *(__half2*)&u.x;
    __half2 h1 = *(__half2*)&u.y;
    float2 f0 = __half22float2(h0);
    float2 f1 = __half22float2(h1);
    return make_float4(f0.x, f0.y, f1.x, f1.y);
}

// ---------------- CSR build -------------------------------------------------
__global__ void k_count(const int* __restrict__ dst_idx) {
    int gw = blockIdx.x * blockDim.x + threadIdx.x;
    if (gw >= RR * EE) return;
    int r = gw / EE;
    atomicAdd(&g_cnt[r * NN + dst_idx[gw]], 1);
}

__global__ __launch_bounds__(SCAN_BLK) void k_scan1() {
    __shared__ int s[SCAN_BLK];
    int t = threadIdx.x;
    int i = blockIdx.x * SCAN_BLK + t;
    int v = (i < NTOT) ? g_cnt[i] : 0;
    s[t] = v;
    __syncthreads();
#pragma unroll
    for (int d = 1; d < SCAN_BLK; d <<= 1) {
        int x = (t >= d) ? s[t - d] : 0;
        __syncthreads();
        s[t] += x;
        __syncthreads();
    }
    if (i < NTOT) g_off[i] = s[t] - v;          // exclusive
    if (t == SCAN_BLK - 1) g_bsum[blockIdx.x] = s[t];
}

__global__ __launch_bounds__(512) void k_scan2() {
    __shared__ int s[512];
    int t = threadIdx.x;
    int v = (t < NBLK) ? g_bsum[t] : 0;
    s[t] = v;
    __syncthreads();
#pragma unroll
    for (int d = 1; d < 512; d <<= 1) {
        int x = (t >= d) ? s[t - d] : 0;
        __syncthreads();
        s[t] += x;
        __syncthreads();
    }
    g_bpre[t] = s[t] - v;                        // exclusive
}

__global__ __launch_bounds__(SCAN_BLK) void k_scan3() {
    int i = blockIdx.x * SCAN_BLK + threadIdx.x;
    if (i < NTOT) g_off[i] += g_bpre[blockIdx.x];
}

__global__ void k_fill(const int* __restrict__ src_idx,
                       const int* __restrict__ dst_idx) {
    int gw = blockIdx.x * blockDim.x + threadIdx.x;
    if (gw >= RR * EE) return;
    int r = gw / EE;
    int pos = atomicAdd(&g_off[r * NN + dst_idx[gw]], 1);
    g_esrc[pos] = src_idx[gw];
}

// ---------------- tf32 tensor-core GEMM: fs/fd = h @ W + b (fp16 out) -------
// Grid = (row-blocks, 6 mats): mats sequential in y; h (51 MB) stays L2-hot
// across all 6 matrices. (R5's transposed grid regressed; reverted.)
__global__ __launch_bounds__(256) void rgat_gemm_tc(
    const float* __restrict__ hmat,
    const float* __restrict__ Wsrc, const float* __restrict__ bsrc,
    const float* __restrict__ Wdst, const float* __restrict__ bdst) {
    const int mat = blockIdx.y;          // 0..5
    const int r   = mat >> 1;
    const bool isdst = (mat & 1);
    const float* W    = (isdst ? Wdst : Wsrc) + r * INF * HD;
    const float* bvec = (isdst ? bdst : bsrc) + r * HD;
    __half* out = (isdst ? g_fd : g_fs) + (size_t)r * NN * HD;

    __shared__ float As[128][36];    // A frag LDS: 4*gid+tig -> conflict-free
    __shared__ float Bs[32][136];    // B frag LDS: 8*tig+gid -> conflict-free

    const int tid  = threadIdx.x;
    const int warp = tid >> 5;
    const int lane = tid & 31;
    const int gid  = lane >> 2;
    const int tig  = lane & 3;
    const int row0 = blockIdx.x * 128;
    const int wrow = warp * 16;

    float c[16][4];
#pragma unroll
    for (int nt = 0; nt < 16; nt++)
#pragma unroll
        for (int j = 0; j < 4; j++) c[nt][j] = 0.f;

    for (int k0 = 0; k0 < INF; k0 += 32) {
#pragma unroll
        for (int i = 0; i < 4; i++) {
            int idx = tid + 256 * i;
            int rr = idx >> 3, cc = (idx & 7) * 4;
            int grow = row0 + rr;
            float4 v = make_float4(0.f, 0.f, 0.f, 0.f);
            if (grow < NN)
                v = *(const float4*)&hmat[(size_t)grow * INF + k0 + cc];
            float4 t;
            t.x = f2tf32(v.x); t.y = f2tf32(v.y);
            t.z = f2tf32(v.z); t.w = f2tf32(v.w);
            *(float4*)&As[rr][cc] = t;
        }
#pragma unroll
        for (int i = 0; i < 4; i++) {
            int idx = tid + 256 * i;
            int kr = idx >> 5, cc = (idx & 31) * 4;
            float4 v = *(const float4*)&W[(size_t)(k0 + kr) * HD + cc];
            float4 t;
            t.x = f2tf32(v.x); t.y = f2tf32(v.y);
            t.z = f2tf32(v.z); t.w = f2tf32(v.w);
            *(float4*)&Bs[kr][cc] = t;
        }
        __syncthreads();
#pragma unroll
        for (int ks = 0; ks < 4; ks++) {
            const int kk = ks * 8;
            uint32_t a0 = __float_as_uint(As[wrow + gid    ][kk + tig    ]);
            uint32_t a1 = __float_as_uint(As[wrow + gid + 8][kk + tig    ]);
            uint32_t a2 = __float_as_uint(As[wrow + gid    ][kk + tig + 4]);
            uint32_t a3 = __float_as_uint(As[wrow + gid + 8][kk + tig + 4]);
#pragma unroll
            for (int nt = 0; nt < 16; nt++) {
                const int n = nt * 8 + gid;
                uint32_t b0 = __float_as_uint(Bs[kk + tig    ][n]);
                uint32_t b1 = __float_as_uint(Bs[kk + tig + 4][n]);
                mma_tf32(c[nt], a0, a1, a2, a3, b0, b1);
            }
        }
        __syncthreads();
    }

    // Store with bias as __half2 (STG.32 per 2 cols)
    const int orow = row0 + wrow + gid;
#pragma unroll
    for (int nt = 0; nt < 16; nt++) {
        const int col = nt * 8 + tig * 2;
        float2 bb = *(const float2*)&bvec[col];
        if (orow < NN) {
            __half2 v = __floats2half2_rn(c[nt][0] + bb.x, c[nt][1] + bb.y);
            *(__half2*)&out[(size_t)orow * HD + col] = v;
        }
        if (orow + 8 < NN) {
            __half2 v = __floats2half2_rn(c[nt][2] + bb.x, c[nt][3] + bb.y);
            *(__half2*)&out[(size_t)(orow + 8) * HD + col] = v;
        }
    }
}

// ---------------- pull-mode aggregation: warp per destination node ----------
// fp16 fs rows: 256 B per gather (LDG.64 per lane). Depth-2 rolling prefetch
// (the structure that benched 576 us). Math in fp32.
__global__ __launch_bounds__(256) void rgat_agg(
    const float* __restrict__ attn, const float* __restrict__ bias,
    float* __restrict__ out) {
    const int dstn = (blockIdx.x * blockDim.x + threadIdx.x) >> 5;
    const int lane = threadIdx.x & 31;
    if (dstn >= NN) return;

    float4 tot;
    {   // start from summed bias
        float4 b0 = ((const float4*)(bias         ))[lane];
        float4 b1 = ((const float4*)(bias +     HD))[lane];
        float4 b2 = ((const float4*)(bias + 2 * HD))[lane];
        tot = make_float4(b0.x + b1.x + b2.x, b0.y + b1.y + b2.y,
                          b0.z + b1.z + b2.z, b0.w + b1.w + b2.w);
    }

#pragma unroll
    for (int r = 0; r < RR; r++) {
        const int bkt = r * NN + dstn;
        const int end = g_off[bkt];          // post-fill == bucket end
        const int cnt = g_cnt[bkt];
        if (cnt == 0) continue;
        const int beg = end - cnt;

        const float4 fd4 = ldh4(g_fd + (size_t)bkt * HD + lane * 4);
        const float4 av  = ((const float4*)(attn + r * HD))[lane];
        const __half* fsr = g_fs + (size_t)r * NN * HD;

        float4 acc = make_float4(0.f, 0.f, 0.f, 0.f);
        float den = 0.f;

        for (int e0 = beg; e0 < end; e0 += 32) {
            const int m = min(32, end - e0);
            int mysrc = (lane < m) ? g_esrc[e0 + lane] : 0;

            // rolling depth-2 prefetch
            int s0 = __shfl_sync(0xFFFFFFFFu, mysrc, 0);
            float4 cur = ldh4(fsr + (size_t)s0 * HD + lane * 4);
            for (int j = 0; j < m; j++) {
                float4 nxt;
                if (j + 1 < m) {
                    int sn = __shfl_sync(0xFFFFFFFFu, mysrc, j + 1);
                    nxt = ldh4(fsr + (size_t)sn * HD + lane * 4);
                }
                float4 v;
                v.x = cur.x + fd4.x; v.x = v.x > 0.f ? v.x : NEG * v.x;
                v.y = cur.y + fd4.y; v.y = v.y > 0.f ? v.y : NEG * v.y;
                v.z = cur.z + fd4.z; v.z = v.z > 0.f ? v.z : NEG * v.z;
                v.w = cur.w + fd4.w; v.w = v.w > 0.f ? v.w : NEG * v.w;
                float p = v.x * av.x + v.y * av.y + v.z * av.z + v.w * av.w;
                p += __shfl_xor_sync(0xFFFFFFFFu, p, 4);
                p += __shfl_xor_sync(0xFFFFFFFFu, p, 2);
                p += __shfl_xor_sync(0xFFFFFFFFu, p, 1);
                const float ex = __expf(p);   // shift-free softmax (logits small)
                den   += ex;
                acc.x += ex * cur.x;
                acc.y += ex * cur.y;
                acc.z += ex * cur.z;
                acc.w += ex * cur.w;
                cur = nxt;
            }
        }
        const float inv = 1.f / den;          // cnt>0 => den>0
        tot.x += acc.x * inv;
        tot.y += acc.y * inv;
        tot.z += acc.z * inv;
        tot.w += acc.w * inv;
    }
    ((float4*)(out + (size_t)dstn * HD))[lane] = tot;
}

// ---------------- launch -----------------------------------------------------
extern "C" void kernel_launch(void* const* d_in, const int* in_sizes, int n_in,
                              void* d_out, int out_size) {
    const float* h     = (const float*)d_in[0];
    const float* W_src = (const float*)d_in[1];
    const float* b_src = (const float*)d_in[2];
    const float* W_dst = (const float*)d_in[3];
    const float* b_dst = (const float*)d_in[4];
    const float* attn  = (const float*)d_in[5];
    const float* bias  = (const float*)d_in[6];
    const int*   src   = (const int*)d_in[7];
    const int*   dst   = (const int*)d_in[8];
    float* out = (float*)d_out;

    const int eblk = (RR * EE + 255) / 256;

    // CSR build (counting sort by (r,dst))
    void* cnt_ptr = nullptr;
    cudaGetSymbolAddress(&cnt_ptr, g_cnt);
    cudaMemsetAsync(cnt_ptr, 0, NTOT * sizeof(int));
    k_count<<<eblk, 256>>>(dst);
    k_scan1<<<NBLK, SCAN_BLK>>>();
    k_scan2<<<1, 512>>>();
    k_scan3<<<NBLK, SCAN_BLK>>>();
    k_fill<<<eblk, 256>>>(src, dst);

    // fs/fd tf32 tensor-core GEMMs (row-blocks fast, mats slow — R4 layout)
    dim3 ggrid((NN + 127) / 128, 2 * RR);
    rgat_gemm_tc<<<ggrid, 256>>>(h, W_src, b_src, W_dst, b_dst);

    // pull-mode aggregation: warp per destination node
    rgat_agg<<<(NN * 32 + 255) / 256, 256>>>(attn, bias, out);
}